// round 3
// baseline (speedup 1.0000x reference)
#include <cuda_runtime.h>

// Scalar damped-Newton minimization of a degree-6 polynomial (serial, 1 thread).
// Semantics match the JAX reference loop exactly:
//   do { g=d1(x); h=d2(x); step = h>0 ? g/h : 0.1g; x-=step; g2=d1(x)^2 }
//   while (g2 > 1e-12 && it < 100)
// Optimizations vs R1:
//  - reuse g_new from the end of iteration k as g of iteration k+1 (reference
//    recomputes the identical value) -> one d1 eval per iter instead of two
//  - Estrin evaluation: 12-cyc dependent chains instead of 20-cyc Horner
//  - rcp.approx.f32 instead of full-precision division (step accuracy only
//    affects the path; fixed point + exit test use exact FFMA evals)

#define MAX_ITER 100
#define GRAD_SQ_TOL 1e-12f

__device__ __forceinline__ float fast_rcp(float v) {
    float r;
    asm("rcp.approx.f32 %0, %1;" : "=f"(r) : "f"(v));
    return r;
}

__global__ void polymin_kernel(const float* __restrict__ poly,
                               const float* __restrict__ x_init,
                               float* __restrict__ out) {
    // 7 coefficients, lowest-degree-first
    float c0 = poly[0], c1 = poly[1], c2 = poly[2], c3 = poly[3],
          c4 = poly[4], c5 = poly[5], c6 = poly[6];

    // d1 = p' (6 coeffs), d2 = p'' (5 coeffs)
    const float a0 = c1 * 1.0f, a1 = c2 * 2.0f, a2 = c3 * 3.0f,
                a3 = c4 * 4.0f, a4 = c5 * 5.0f, a5 = c6 * 6.0f;
    const float b0 = a1 * 1.0f, b1 = a2 * 2.0f, b2 = a3 * 3.0f,
                b3 = a4 * 4.0f, b4 = a5 * 5.0f;

    float x = x_init[0];

    // g = d1(x) for the first body execution (reference always runs >=1 iter:
    // initial g2 = inf). Estrin: (a0+a1 x) + x2*(a2+a3 x) + x4*(a4+a5 x)
    float x2 = x * x;
    float g  = fmaf(fmaf(a5, x, a4), x2, fmaf(a3, x, a2));
    g        = fmaf(g, x2, fmaf(a1, x, a0));

    #pragma unroll 1
    for (int it = 0; it < MAX_ITER; ++it) {
        // h = d2(x): (b0+b1 x) + x2*(b2+b3 x) + x4*b4
        float h  = fmaf(fmaf(b4, x2, fmaf(b3, x, b2)), x2, fmaf(b1, x, b0));
        // step = h>0 ? g/h : 0.1*g   (approx rcp; see header comment)
        float mul = (h > 0.0f) ? fast_rcp(h) : 0.1f;
        x = fmaf(-g, mul, x);
        // g_new = d1(x_new); exit when g_new^2 <= tol
        x2 = x * x;
        g  = fmaf(fmaf(a5, x, a4), x2, fmaf(a3, x, a2));
        g  = fmaf(g, x2, fmaf(a1, x, a0));
        if (!(g * g > GRAD_SQ_TOL)) break;
    }

    out[0] = x;
}

extern "C" void kernel_launch(void* const* d_in, const int* in_sizes, int n_in,
                              void* d_out, int out_size) {
    const float* poly   = (const float*)d_in[0];   // 7 fp32
    const float* x_init = (const float*)d_in[1];   // 1 fp32
    polymin_kernel<<<1, 1>>>(poly, x_init, (float*)d_out);
}

// round 4
// speedup vs baseline: 1.0750x; 1.0750x over previous
#include <cuda_runtime.h>

// Scalar damped-Newton minimization of a degree-6 polynomial (serial, 1 thread).
// Matches the JAX reference fixed point:
//   loop: g=d1(x); h=d2(x); step = h>0 ? g/h : 0.1*g; x -= step
//   exit when d1(x)^2 <= 1e-12 or 100 iterations.
// R3 changes (exit-check chain was the bottleneck, ~30 cyc/iter serialized):
//  - Newton body unrolled in blocks of 4; convergence checked once per block
//    (extra <=3 steps near the fixed point move x by ~|g/h| ~ 1e-6 -> well
//    inside the 1e-3 tolerance, and the iteration contracts at a minimum).
//  - step multiplier via unconditional rcp.approx + FSEL (predicate consumed
//    as data, 4 cyc, instead of 13-cyc guarded MUFU).
//  - x-update chain ~36 cyc/iter: h@12 -> rcp@28 -> FSEL@32 -> FMA@36.

#define GRAD_SQ_TOL 1e-12f

__device__ __forceinline__ float fast_rcp(float v) {
    float r;
    asm("rcp.approx.f32 %0, %1;" : "=f"(r) : "f"(v));
    return r;
}

__global__ void polymin_kernel(const float* __restrict__ poly,
                               const float* __restrict__ x_init,
                               float* __restrict__ out) {
    // 7 coefficients, lowest-degree-first
    const float c1 = poly[1], c2 = poly[2], c3 = poly[3],
                c4 = poly[4], c5 = poly[5], c6 = poly[6];

    // d1 = p' (6 coeffs), d2 = p'' (5 coeffs)
    const float a0 = c1,        a1 = c2 * 2.0f, a2 = c3 * 3.0f,
                a3 = c4 * 4.0f, a4 = c5 * 5.0f, a5 = c6 * 6.0f;
    const float b0 = a1,        b1 = a2 * 2.0f, b2 = a3 * 3.0f,
                b3 = a4 * 4.0f, b4 = a5 * 5.0f;

    float x = x_init[0];

    #pragma unroll 1
    for (int blk = 0; blk < 25; ++blk) {
        #pragma unroll
        for (int u = 0; u < 4; ++u) {
            const float x2 = x * x;
            // g = d1(x), Estrin
            float g = fmaf(fmaf(a5, x, a4), x2, fmaf(a3, x, a2));
            g = fmaf(g, x2, fmaf(a1, x, a0));
            // h = d2(x), Estrin
            const float h = fmaf(fmaf(b4, x2, fmaf(b3, x, b2)), x2,
                                 fmaf(b1, x, b0));
            // mul = h>0 ? 1/h : 0.1  (rcp off-predicate, FSEL on pred-as-data)
            const float r = fast_rcp(h);
            const float mul = (h > 0.0f) ? r : 0.1f;
            x = fmaf(-g, mul, x);
        }
        // convergence check once per 4 Newton steps
        const float x2 = x * x;
        float gn = fmaf(fmaf(a5, x, a4), x2, fmaf(a3, x, a2));
        gn = fmaf(gn, x2, fmaf(a1, x, a0));
        if (!(gn * gn > GRAD_SQ_TOL)) break;
    }

    out[0] = x;
}

extern "C" void kernel_launch(void* const* d_in, const int* in_sizes, int n_in,
                              void* d_out, int out_size) {
    const float* poly   = (const float*)d_in[0];   // 7 fp32
    const float* x_init = (const float*)d_in[1];   // 1 fp32
    polymin_kernel<<<1, 1>>>(poly, x_init, (float*)d_out);
}